// round 3
// baseline (speedup 1.0000x reference)
#include <cuda_runtime.h>

#define NL 7
#define BATCH 524288

// Output layout (reference returns (ts, quats)):
//   ts:    [NL, BATCH, 3]  floats at out[0 ..)
//   quats: [NL, BATCH, 4]  floats at out[NL*BATCH*3 ..)  in (x,y,z,w) order

__global__ __launch_bounds__(256)
void fk_quat_kernel(const float* __restrict__ q,
                    const float* __restrict__ rot_fixed,
                    const float* __restrict__ trans_fixed,
                    float* __restrict__ out)
{
    __shared__ float4 sQF[NL];   // fixed rotation as quaternion (x,y,z,w)
    __shared__ float  sTF[NL * 3];

    {
        int tid = threadIdx.x;
        if (tid < NL) {
            const float* R = rot_fixed + tid * 9;
            float r00 = R[0], r01 = R[1], r02 = R[2];
            float r10 = R[3], r11 = R[4], r12 = R[5];
            float r20 = R[6], r21 = R[7], r22 = R[8];
            const float eps = 1e-9f;
            float qw = 0.5f * sqrtf(fmaxf(1.f + r00 + r11 + r22, eps));
            float qx = 0.5f * sqrtf(fmaxf(1.f + r00 - r11 - r22, eps));
            float qy = 0.5f * sqrtf(fmaxf(1.f - r00 + r11 - r22, eps));
            float qz = 0.5f * sqrtf(fmaxf(1.f - r00 - r11 + r22, eps));
            qx = copysignf(qx, r21 - r12);
            qy = copysignf(qy, r02 - r20);
            qz = copysignf(qz, r10 - r01);
            sQF[tid] = make_float4(qx, qy, qz, qw);
        }
        if (tid < NL * 3) sTF[tid] = trans_fixed[tid];
    }
    __syncthreads();

    int b = blockIdx.x * blockDim.x + threadIdx.x;
    if (b >= BATCH) return;

    float qv[NL];
    #pragma unroll
    for (int i = 0; i < NL; i++) qv[i] = __ldg(&q[b * NL + i]);

    // Parent world pose: quaternion (identity) + translation (zero)
    float px = 0.f, py = 0.f, pz = 0.f, pw = 1.f;
    float tx = 0.f, ty = 0.f, tz = 0.f;

    float*  ts_out = out;                                      // [NL, BATCH, 3]
    float4* qu_out = (float4*)(out + (size_t)NL * BATCH * 3);  // [NL, BATCH, 4]

    #pragma unroll
    for (int l = 0; l < NL; l++) {
        // ---- translation update: t += Rp @ tf  (rotate tf by parent quat) ----
        {
            float vx = sTF[l * 3 + 0], vy = sTF[l * 3 + 1], vz = sTF[l * 3 + 2];
            // c1 = u x v
            float c1x = fmaf(py, vz, -pz * vy);
            float c1y = fmaf(pz, vx, -px * vz);
            float c1z = fmaf(px, vy, -py * vx);
            // c2 = w*c1 + u x c1
            float c2x = fmaf(pw, c1x, fmaf(py, c1z, -pz * c1y));
            float c2y = fmaf(pw, c1y, fmaf(pz, c1x, -px * c1z));
            float c2z = fmaf(pw, c1z, fmaf(px, c1y, -py * c1x));
            // t_new = t + v + 2*c2
            tx = fmaf(2.f, c2x, tx + vx);
            ty = fmaf(2.f, c2y, ty + vy);
            tz = fmaf(2.f, c2z, tz + vz);
        }

        // ---- orientation update: p = p (x) qf[l] (x) q_axis ----
        {
            float4 f = sQF[l];
            // m = p (x) f   (Hamilton product, (x,y,z,w))
            float mw = fmaf(pw, f.w, -fmaf(px, f.x, fmaf(py, f.y, pz * f.z)));
            float mx = fmaf(pw, f.x, fmaf(px, f.w, fmaf(py, f.z, -pz * f.y)));
            float my = fmaf(pw, f.y, fmaf(-px, f.z, fmaf(py, f.w, pz * f.x)));
            float mz = fmaf(pw, f.z, fmaf(px, f.y, fmaf(-py, f.x, pz * f.w)));

            float s, c;
            __sincosf(0.5f * qv[l], &s, &c);

            if ((l & 1) == 0) {
                // axis z: qa = (0,0,s,c)
                pw = fmaf(mw, c, -mz * s);
                px = fmaf(mx, c,  my * s);
                py = fmaf(my, c, -mx * s);
                pz = fmaf(mw, s,  mz * c);
            } else {
                // axis y: qa = (0,s,0,c)
                pw = fmaf(mw, c, -my * s);
                px = fmaf(mx, c, -mz * s);
                py = fmaf(mw, s,  my * c);
                pz = fmaf(mz, c,  mx * s);
            }
        }

        // ---- write position ----
        size_t tbase = ((size_t)l * BATCH + b) * 3;
        ts_out[tbase + 0] = tx;
        ts_out[tbase + 1] = ty;
        ts_out[tbase + 2] = tz;

        // ---- write canonical quaternion (w >= 0), matching reference signs ----
        float sgn = (pw < 0.f) ? -1.f : 1.f;
        qu_out[(size_t)l * BATCH + b] =
            make_float4(sgn * px, sgn * py, sgn * pz, sgn * pw);
    }
}

extern "C" void kernel_launch(void* const* d_in, const int* in_sizes, int n_in,
                              void* d_out, int out_size) {
    const float* q           = (const float*)d_in[0];
    const float* rot_fixed   = (const float*)d_in[1];
    const float* trans_fixed = (const float*)d_in[2];
    float* out = (float*)d_out;

    const int threads = 256;
    const int blocks = (BATCH + threads - 1) / threads;
    fk_quat_kernel<<<blocks, threads>>>(q, rot_fixed, trans_fixed, out);
}